// round 4
// baseline (speedup 1.0000x reference)
#include <cuda_runtime.h>
#include <stdint.h>

#define NMAX 50000
#define EMAX 1600000
#define NH   9
#define NC   8
#define HCc  72
#define PAD  12          // padded per-node head-row (48B, 16B-aligned)
#define NEG_SLOPE 0.2f

// ---------------- device scratch (static globals; no runtime allocation) ----
__device__ __align__(16) float    g_h[NMAX * HCc];            // linear output [N,72]
__device__ __align__(16) float    g_as[NMAX * PAD];           // a_src [N,9] padded
__device__ __align__(16) float    g_ad[NMAX * PAD];           // a_dst [N,9] padded
__device__ __align__(16) unsigned g_menc[NMAX * PAD];         // encoded max, later float m
__device__ __align__(16) float    g_denom[NMAX * PAD];        // softmax denominator
__device__ __align__(16) float    g_outacc[NMAX * HCc];       // weighted-sum accumulator
__device__ __align__(16) float    g_alpha[(size_t)NH * EMAX]; // per-edge raw scores, SoA [H][E]
__device__ __align__(16) float    g_concat[NMAX * 3 * HCc];   // [N,216]
__device__ __align__(16) int      g_src[EMAX];                // decoded src indices
__device__ __align__(16) int      g_dst[EMAX];                // decoded dst indices
__device__ int g_is64;                                        // 1 if edge_index is int64

// monotone float<->uint encoding for atomicMax on floats
__device__ __forceinline__ unsigned fenc(float f) {
    unsigned u = __float_as_uint(f);
    return (u & 0x80000000u) ? ~u : (u | 0x80000000u);
}
__device__ __forceinline__ float fdec(unsigned u) {
    return __uint_as_float((u & 0x80000000u) ? (u & 0x7fffffffu) : ~u);
}
__device__ __forceinline__ float lrelu(float x) {
    return x > 0.f ? x : NEG_SLOPE * x;
}
// vector atomic add (sm_90+): one 16B red instead of 4 scalar atomics
__device__ __forceinline__ void red4(float* p, float4 v) {
    asm volatile("red.global.add.v4.f32 [%0], {%1,%2,%3,%4};"
                 :: "l"(p), "f"(v.x), "f"(v.y), "f"(v.z), "f"(v.w) : "memory");
}

// ---------------- K0a: detect edge_index dtype (int64 vs int32) --------------
// If the buffer is int64 (values < N << 2^31), every odd 32-bit word of the
// first entries is 0. Genuine int32 data has random node-ids there.
__global__ void k_detect(const int* __restrict__ ei32, int E) {
    __shared__ int ok;
    int t = threadIdx.x;
    if (t == 0) ok = 1;
    __syncthreads();
    int cnt = E < 512 ? E : 512;
    bool z = true;
    for (int i = t; i < cnt; i += blockDim.x)
        if (ei32[2 * i + 1] != 0) z = false;
    if (!z) ok = 0;
    __syncthreads();
    if (t == 0) g_is64 = ok;
}

// ---------------- K0b: decode + clamp edge indices to int32 ------------------
__global__ void k_convert(const int* __restrict__ ei32, int E, int n) {
    int e = blockIdx.x * blockDim.x + threadIdx.x;
    if (e >= E) return;
    long long s, d;
    if (g_is64) {
        const long long* p = (const long long*)ei32;
        s = p[e]; d = p[(size_t)E + e];
    } else {
        s = ei32[e]; d = ei32[(size_t)E + e];
    }
    if (s < 0 || s >= n) s = 0;   // safety clamp (no-op for valid data)
    if (d < 0 || d >= n) d = 0;
    g_src[e] = (int)s;
    g_dst[e] = (int)d;
}

// ---------------- K1: h = x @ W  (tiled, W in smem) --------------------------
__global__ __launch_bounds__(288) void k_linear(const float* __restrict__ x,
                                                const float* __restrict__ W, int n) {
    __shared__ float Ws[128 * HCc];   // 36 KB
    __shared__ float xs[16][128];     // 8 KB
    int t = threadIdx.x;
    for (int i = t; i < 128 * HCc; i += 288) Ws[i] = W[i];
    int base = blockIdx.x * 16;
    for (int i = t; i < 16 * 128; i += 288) {
        int r = i >> 7, k = i & 127;
        xs[r][k] = (base + r < n) ? x[(size_t)(base + r) * 128 + k] : 0.f;
    }
    __syncthreads();
    int col = t % HCc;
    int r0  = t / HCc;   // 0..3
    #pragma unroll
    for (int rr = 0; rr < 4; rr++) {
        int r = rr * 4 + r0;
        int node = base + r;
        if (node < n) {
            float acc = 0.f;
            #pragma unroll 16
            for (int k = 0; k < 128; k++) acc += xs[r][k] * Ws[k * HCc + col];
            g_h[(size_t)node * HCc + col] = acc;
        }
    }
}

// ---------------- K2: per (node,head) attention scalars + self-loop max init -
__global__ void k_scores(const float* __restrict__ att_s,
                         const float* __restrict__ att_d, int n) {
    int i = blockIdx.x * blockDim.x + threadIdx.x;
    if (i >= n * NH) return;
    int node = i / NH, hh = i % NH;
    const float* hp = g_h + (size_t)node * HCc + hh * NC;
    float as = 0.f, ad = 0.f;
    #pragma unroll
    for (int c = 0; c < NC; c++) {
        float v = hp[c];
        as += v * att_s[hh * NC + c];
        ad += v * att_d[hh * NC + c];
    }
    g_as[node * PAD + hh] = as;
    g_ad[node * PAD + hh] = ad;
    g_menc[node * PAD + hh] = fenc(lrelu(as + ad));  // self-loop seeds the max
}

// ---------------- K3: per edge: score + atomicMax into dst -------------------
__global__ void k_edge_max(int E) {
    int e = blockIdx.x * blockDim.x + threadIdx.x;
    if (e >= E) return;
    int s = g_src[e], d = g_dst[e];
    const float* as = g_as + (size_t)s * PAD;
    const float* ad = g_ad + (size_t)d * PAD;
    unsigned* mp = g_menc + (size_t)d * PAD;
    #pragma unroll
    for (int hh = 0; hh < NH; hh++) {
        float a = lrelu(as[hh] + ad[hh]);
        g_alpha[(size_t)hh * E + e] = a;   // SoA: coalesced write/read
        atomicMax(mp + hh, fenc(a));
    }
}

// ---------------- K4: per node: decode m, init denom & outacc with self-loop -
__global__ void k_node_init(int n) {
    int i = blockIdx.x * blockDim.x + threadIdx.x;
    if (i >= n * NH) return;
    int node = i / NH, hh = i % NH;
    int idx = node * PAD + hh;
    float m = fdec(g_menc[idx]);
    g_menc[idx] = __float_as_uint(m);   // store decoded m for the edge pass
    float sa = lrelu(g_as[idx] + g_ad[idx]);
    float e0 = __expf(sa - m);
    g_denom[idx] = e0;
    const float* hp = g_h + (size_t)node * HCc + hh * NC;
    float* op = g_outacc + (size_t)node * HCc + hh * NC;
    #pragma unroll
    for (int c = 0; c < NC; c++) op[c] = e0 * hp[c];
}

// ---------------- K5: per edge: exp weight, denom & feature scatter-add ------
__global__ void k_edge_acc(int E) {
    int e = blockIdx.x * blockDim.x + threadIdx.x;
    if (e >= E) return;
    int s = g_src[e], d = g_dst[e];
    const float* mrow = (const float*)(g_menc + (size_t)d * PAD);
    float* drow = g_denom + (size_t)d * PAD;
    float w[NH];
    #pragma unroll
    for (int hh = 0; hh < NH; hh++) {
        float a = g_alpha[(size_t)hh * E + e];
        w[hh] = __expf(a - mrow[hh]);
        atomicAdd(drow + hh, w[hh]);
    }
    const float4* hs = (const float4*)(g_h + (size_t)s * HCc);
    float* oa = g_outacc + (size_t)d * HCc;
    #pragma unroll
    for (int j = 0; j < 18; j++) {       // 72 floats = 18 float4; head = j/2
        float4 v = hs[j];
        float ww = w[j >> 1];
        v.x *= ww; v.y *= ww; v.z *= ww; v.w *= ww;
        red4(oa + 4 * j, v);
    }
}

// ---------------- K6: normalize + bias -> concat slot ------------------------
__global__ void k_normalize(const float* __restrict__ bias, int n, int gofs) {
    int i = blockIdx.x * blockDim.x + threadIdx.x;
    if (i >= n * HCc) return;
    int node = i / HCc, col = i % HCc;
    float v = g_outacc[i] / (g_denom[node * PAD + (col >> 3)] + 1e-16f) + bias[col];
    g_concat[(size_t)node * (3 * HCc) + gofs + col] = v;
}

// ---------------- K7: relu -> [216,2] FNN -> softmax -------------------------
__global__ void k_fnn(const float* __restrict__ fW, const float* __restrict__ fb,
                      float* __restrict__ out, int n) {
    __shared__ float Wl[3 * HCc * 2];
    int t = threadIdx.x;
    for (int i = t; i < 3 * HCc * 2; i += blockDim.x) Wl[i] = fW[i];
    __syncthreads();
    int node = blockIdx.x * blockDim.x + t;
    if (node >= n) return;
    const float* row = g_concat + (size_t)node * (3 * HCc);
    float l0 = fb[0], l1 = fb[1];
    #pragma unroll 8
    for (int i = 0; i < 3 * HCc; i++) {
        float v = row[i];
        v = v > 0.f ? v : 0.f;
        l0 += v * Wl[2 * i];
        l1 += v * Wl[2 * i + 1];
    }
    float mm = fmaxf(l0, l1);
    float e0 = __expf(l0 - mm), e1 = __expf(l1 - mm);
    float inv = 1.f / (e0 + e1);
    out[2 * node]     = e0 * inv;
    out[2 * node + 1] = e1 * inv;
}

// ---------------- host: classify inputs by size, launch pipeline -------------
extern "C" void kernel_launch(void* const* d_in, const int* in_sizes, int n_in,
                              void* d_out, int out_size) {
    const float* x[3]   = {0, 0, 0};
    const int*   ei[3]  = {0, 0, 0};
    const float* W[3]   = {0, 0, 0};
    const float* asr[3] = {0, 0, 0};
    const float* adr[3] = {0, 0, 0};
    const float* b[3]   = {0, 0, 0};
    const float* fW = 0; const float* fb = 0;
    int ix = 0, ie = 0, iw = 0, cur = 0, c72 = 0;
    long long xsz = 0, esz = 0;

    for (int i = 0; i < n_in; i++) {
        long long sz = in_sizes[i];
        if (sz >= 1000000) {
            // x = N*128 f32 (6.4M elems); edge_index = 2*E (3.2M elems either dtype)
            if (sz > 4000000) {
                if (ix < 3) { x[ix++] = (const float*)d_in[i]; xsz = sz; }
            } else {
                if (ie < 3) { ei[ie++] = (const int*)d_in[i]; esz = sz; }
            }
        } else if (sz == 128 * HCc) {          // 9216: W -> starts a group
            if (iw < 3) { W[iw] = (const float*)d_in[i]; cur = iw; iw++; c72 = 0; }
        } else if (sz == HCc) {                // 72: att_src, att_dst, b in order
            if (c72 == 0)      asr[cur] = (const float*)d_in[i];
            else if (c72 == 1) adr[cur] = (const float*)d_in[i];
            else               b[cur]   = (const float*)d_in[i];
            c72++;
        } else if (sz == 3 * HCc * 2) {        // 432
            fW = (const float*)d_in[i];
        } else if (sz == 2) {
            fb = (const float*)d_in[i];
        }
    }

    int N = (int)(xsz / 128);
    int E = (int)(esz / 2);
    float* out = (float*)d_out;

    int bNH  = (N * NH  + 255) / 256;
    int bE   = (E       + 255) / 256;
    int bNHC = (N * HCc + 255) / 256;

    for (int g = 0; g < 3; g++) {
        k_detect   <<<1, 256>>>(ei[g], E);
        k_convert  <<<bE, 256>>>(ei[g], E, N);
        k_linear   <<<(N + 15) / 16, 288>>>(x[g], W[g], N);
        k_scores   <<<bNH, 256>>>(asr[g], adr[g], N);
        k_edge_max <<<bE, 256>>>(E);
        k_node_init<<<bNH, 256>>>(N);
        k_edge_acc <<<bE, 256>>>(E);
        k_normalize<<<bNHC, 256>>>(b[g], N, g * HCc);
    }
    k_fnn<<<(N + 255) / 256, 256>>>(fW, fb, out, N);
    (void)out_size;
}

// round 5
// speedup vs baseline: 1.3340x; 1.3340x over previous
#include <cuda_runtime.h>
#include <stdint.h>

#define NMAX 50000
#define EMAX 1600000
#define NH   9
#define HCc  72
#define HROW 88          // 72 feat + 9 a_src + 7 pad -> 352B, 32B-sector aligned
#define PAD  12
#define NEG_SLOPE 0.2f

// ---------------- device scratch ---------------------------------------------
__device__ __align__(16) float g_h[(size_t)NMAX * HROW];   // [h(72) | a_src(9) | pad]
__device__ __align__(16) float g_ad[NMAX * PAD];           // a_dst per node/head
__device__ __align__(16) float g_concat[NMAX * 3 * HCc];   // [N,216]
__device__ int g_src[EMAX];
__device__ int g_dst[EMAX];
__device__ int g_deg[NMAX];
__device__ int g_off[NMAX + 1];
__device__ int g_cursor[NMAX];
__device__ int g_csr[EMAX];                                // src ids grouped by dst
__device__ int g_is64;

__device__ __forceinline__ float lrelu(float x) {
    return x > 0.f ? x : NEG_SLOPE * x;
}

// ---------------- K0a: detect edge_index dtype (int64 vs int32) --------------
__global__ void k_detect(const int* __restrict__ ei32, int E) {
    __shared__ int ok;
    int t = threadIdx.x;
    if (t == 0) ok = 1;
    __syncthreads();
    int cnt = E < 512 ? E : 512;
    bool z = true;
    for (int i = t; i < cnt; i += blockDim.x)
        if (ei32[2 * i + 1] != 0) z = false;
    if (!z) ok = 0;
    __syncthreads();
    if (t == 0) g_is64 = ok;
}

// ---------------- K0b: zero per-graph degree counters -------------------------
__global__ void k_zero(int n) {
    int i = blockIdx.x * blockDim.x + threadIdx.x;
    if (i < n) g_deg[i] = 0;
}

// ---------------- K0c: decode + clamp indices, histogram dst ------------------
__global__ void k_convert_hist(const int* __restrict__ ei32, int E, int n) {
    int e = blockIdx.x * blockDim.x + threadIdx.x;
    if (e >= E) return;
    long long s, d;
    if (g_is64) {
        const long long* p = (const long long*)ei32;
        s = p[e]; d = p[(size_t)E + e];
    } else {
        s = ei32[e]; d = ei32[(size_t)E + e];
    }
    if (s < 0 || s >= n) s = 0;
    if (d < 0 || d >= n) d = 0;
    g_src[e] = (int)s;
    g_dst[e] = (int)d;
    atomicAdd(&g_deg[(int)d], 1);
}

// ---------------- K0d: single-block exclusive scan of degrees -----------------
__global__ void k_scan(int n) {
    __shared__ int part[1024];
    int t = threadIdx.x;
    int per = (n + 1023) / 1024;
    int b0 = t * per;
    int hi = min(b0 + per, n);
    int sum = 0;
    for (int i = b0; i < hi; i++) sum += g_deg[i];
    part[t] = sum;
    __syncthreads();
    for (int ofs = 1; ofs < 1024; ofs <<= 1) {     // inclusive Hillis-Steele
        int v = (t >= ofs) ? part[t - ofs] : 0;
        __syncthreads();
        part[t] += v;
        __syncthreads();
    }
    int run = (t == 0) ? 0 : part[t - 1];
    for (int i = b0; i < hi; i++) {
        g_off[i] = run;
        g_cursor[i] = run;
        run += g_deg[i];
    }
    if (t == 1023) g_off[n] = run;                  // == total E
}

// ---------------- K0e: scatter src ids into CSR slots -------------------------
__global__ void k_fill(int E) {
    int e = blockIdx.x * blockDim.x + threadIdx.x;
    if (e >= E) return;
    int d = g_dst[e];
    int pos = atomicAdd(&g_cursor[d], 1);
    g_csr[pos] = g_src[e];
}

// ---------------- K1: h = x @ W (tiled, W in smem), write padded rows ---------
__global__ __launch_bounds__(288) void k_linear(const float* __restrict__ x,
                                                const float* __restrict__ W, int n) {
    __shared__ float Ws[128 * HCc];   // 36 KB
    __shared__ float xs[16][128];     // 8 KB
    int t = threadIdx.x;
    for (int i = t; i < 128 * HCc; i += 288) Ws[i] = W[i];
    int base = blockIdx.x * 16;
    for (int i = t; i < 16 * 128; i += 288) {
        int r = i >> 7, k = i & 127;
        xs[r][k] = (base + r < n) ? x[(size_t)(base + r) * 128 + k] : 0.f;
    }
    __syncthreads();
    int col = t % HCc;
    int r0  = t / HCc;   // 0..3
    #pragma unroll
    for (int rr = 0; rr < 4; rr++) {
        int r = rr * 4 + r0;
        int node = base + r;
        if (node < n) {
            float acc = 0.f;
            #pragma unroll 16
            for (int k = 0; k < 128; k++) acc += xs[r][k] * Ws[k * HCc + col];
            g_h[(size_t)node * HROW + col] = acc;
        }
    }
}

// ---------------- K2: attention scalars; a_src packed into h row --------------
__global__ void k_scores(const float* __restrict__ att_s,
                         const float* __restrict__ att_d, int n) {
    int i = blockIdx.x * blockDim.x + threadIdx.x;
    if (i >= n * NH) return;
    int node = i / NH, hh = i % NH;
    const float* hp = g_h + (size_t)node * HROW + hh * 8;
    float as = 0.f, ad = 0.f;
    #pragma unroll
    for (int c = 0; c < 8; c++) {
        float v = hp[c];
        as += v * att_s[hh * 8 + c];
        ad += v * att_d[hh * 8 + c];
    }
    g_h[(size_t)node * HROW + 72 + hh] = as;
    g_ad[node * PAD + hh] = ad;
}

// ---------------- K3: warp-per-dst GAT softmax-aggregate (no atomics) ---------
__global__ __launch_bounds__(256) void k_gat(const float* __restrict__ bias,
                                             int n, int gofs) {
    __shared__ float sw[8][32][13];      // per-warp staged edge weights, pad=13
    int gwarp = (blockIdx.x * 256 + threadIdx.x) >> 5;
    int lane  = threadIdx.x & 31;
    int wib   = threadIdx.x >> 5;
    if (gwarp >= n) return;
    int d = gwarp;
    int beg = g_off[d], end = g_off[d + 1];

    const float* hd = g_h + (size_t)d * HROW;
    float ad_r[NH], aself_w[NH];
    #pragma unroll
    for (int h = 0; h < NH; h++) {
        ad_r[h]    = g_ad[d * PAD + h];                 // uniform loads
        aself_w[h] = __expf(lrelu(hd[72 + h] + ad_r[h]));  // self-loop weight
    }
    int h1 = lane >> 3;            // head owning feature `lane`
    int h2 = (lane + 32) >> 3;     // head owning feature `lane+32`

    float dsum[NH];
    #pragma unroll
    for (int h = 0; h < NH; h++) dsum[h] = 0.f;

    // self-loop initializes the accumulators
    float acc1 = aself_w[h1] * hd[lane];
    float acc2 = aself_w[h2] * hd[lane + 32];
    float acc3 = (lane < 8) ? aself_w[8] * hd[lane + 64] : 0.f;

    for (int cbeg = beg; cbeg < end; cbeg += 32) {
        int ecnt = min(32, end - cbeg);
        int s_mine = 0;
        float wv[NH];
        if (lane < ecnt) {                   // lane-parallel: scores + exp
            s_mine = g_csr[cbeg + lane];
            const float* hs = g_h + (size_t)s_mine * HROW;
            float4 p0 = *(const float4*)(hs + 72);
            float4 p1 = *(const float4*)(hs + 76);
            float  a8 = hs[80];
            float asv[NH] = {p0.x, p0.y, p0.z, p0.w, p1.x, p1.y, p1.z, p1.w, a8};
            #pragma unroll
            for (int h = 0; h < NH; h++) {
                wv[h] = __expf(lrelu(asv[h] + ad_r[h]));
                dsum[h] += wv[h];
            }
        } else {
            #pragma unroll
            for (int h = 0; h < NH; h++) wv[h] = 0.f;
        }
        #pragma unroll
        for (int h = 0; h < NH; h++) sw[wib][lane][h] = wv[h];
        __syncwarp();
        for (int j = 0; j < ecnt; j++) {     // feature-parallel gather/accumulate
            int s = __shfl_sync(0xffffffffu, s_mine, j);
            const float* hs = g_h + (size_t)s * HROW;
            acc1 += sw[wib][j][h1] * hs[lane];
            acc2 += sw[wib][j][h2] * hs[lane + 32];
            if (lane < 8) acc3 += sw[wib][j][8] * hs[lane + 64];
        }
        __syncwarp();
    }

    #pragma unroll
    for (int h = 0; h < NH; h++) {           // cross-lane denominator reduce
        float v = dsum[h];
        #pragma unroll
        for (int ofs = 16; ofs; ofs >>= 1) v += __shfl_xor_sync(0xffffffffu, v, ofs);
        dsum[h] = v + aself_w[h];
    }

    float* orow = g_concat + (size_t)d * (3 * HCc) + gofs;
    orow[lane]      = acc1 / (dsum[h1] + 1e-16f) + bias[lane];
    orow[lane + 32] = acc2 / (dsum[h2] + 1e-16f) + bias[lane + 32];
    if (lane < 8)
        orow[lane + 64] = acc3 / (dsum[8] + 1e-16f) + bias[lane + 64];
}

// ---------------- K4: relu -> [216,2] FNN -> softmax --------------------------
__global__ void k_fnn(const float* __restrict__ fW, const float* __restrict__ fb,
                      float* __restrict__ out, int n) {
    __shared__ float Wl[3 * HCc * 2];
    int t = threadIdx.x;
    for (int i = t; i < 3 * HCc * 2; i += blockDim.x) Wl[i] = fW[i];
    __syncthreads();
    int node = blockIdx.x * blockDim.x + t;
    if (node >= n) return;
    const float* row = g_concat + (size_t)node * (3 * HCc);
    float l0 = fb[0], l1 = fb[1];
    #pragma unroll 8
    for (int i = 0; i < 3 * HCc; i++) {
        float v = row[i];
        v = v > 0.f ? v : 0.f;
        l0 += v * Wl[2 * i];
        l1 += v * Wl[2 * i + 1];
    }
    float mm = fmaxf(l0, l1);
    float e0 = __expf(l0 - mm), e1 = __expf(l1 - mm);
    float inv = 1.f / (e0 + e1);
    out[2 * node]     = e0 * inv;
    out[2 * node + 1] = e1 * inv;
}

// ---------------- host: classify inputs by size, launch pipeline --------------
extern "C" void kernel_launch(void* const* d_in, const int* in_sizes, int n_in,
                              void* d_out, int out_size) {
    const float* x[3]   = {0, 0, 0};
    const int*   ei[3]  = {0, 0, 0};
    const float* W[3]   = {0, 0, 0};
    const float* asr[3] = {0, 0, 0};
    const float* adr[3] = {0, 0, 0};
    const float* b[3]   = {0, 0, 0};
    const float* fW = 0; const float* fb = 0;
    int ix = 0, ie = 0, iw = 0, cur = 0, c72 = 0;
    long long xsz = 0, esz = 0;

    for (int i = 0; i < n_in; i++) {
        long long sz = in_sizes[i];
        if (sz >= 1000000) {
            if (sz > 4000000) {
                if (ix < 3) { x[ix++] = (const float*)d_in[i]; xsz = sz; }
            } else {
                if (ie < 3) { ei[ie++] = (const int*)d_in[i]; esz = sz; }
            }
        } else if (sz == 128 * HCc) {          // 9216: W starts a GAT group
            if (iw < 3) { W[iw] = (const float*)d_in[i]; cur = iw; iw++; c72 = 0; }
        } else if (sz == HCc) {                // 72: att_src, att_dst, b in order
            if (c72 == 0)      asr[cur] = (const float*)d_in[i];
            else if (c72 == 1) adr[cur] = (const float*)d_in[i];
            else               b[cur]   = (const float*)d_in[i];
            c72++;
        } else if (sz == 3 * HCc * 2) {        // 432
            fW = (const float*)d_in[i];
        } else if (sz == 2) {
            fb = (const float*)d_in[i];
        }
    }

    int N = (int)(xsz / 128);
    int E = (int)(esz / 2);
    float* out = (float*)d_out;

    int bNH = (N * NH + 255) / 256;
    int bE  = (E + 255) / 256;
    int bN  = (N + 255) / 256;

    for (int g = 0; g < 3; g++) {
        k_detect      <<<1, 256>>>(ei[g], E);
        k_zero        <<<bN, 256>>>(N);
        k_convert_hist<<<bE, 256>>>(ei[g], E, N);
        k_scan        <<<1, 1024>>>(N);
        k_fill        <<<bE, 256>>>(E);
        k_linear      <<<(N + 15) / 16, 288>>>(x[g], W[g], N);
        k_scores      <<<bNH, 256>>>(asr[g], adr[g], N);
        k_gat         <<<(N + 7) / 8, 256>>>(b[g], N, g * HCc);
    }
    k_fnn<<<bN, 256>>>(fW, fb, out, N);
    (void)out_size;
}

// round 6
// speedup vs baseline: 1.8962x; 1.4214x over previous
#include <cuda_runtime.h>
#include <stdint.h>

#define NMAX 50000
#define EMAX 1600000
#define NG   3
#define NH   9
#define HCc  72
#define HROW 88          // 72 feat + 9 a_src + 7 pad -> 352B, sector aligned
#define PAD  12
#define NEG_SLOPE 0.2f
#define SCAN_CHUNK 1024
#define MAXB ((NG * NMAX + SCAN_CHUNK - 1) / SCAN_CHUNK)   // 147 <= 256

// ---------------- device scratch (3 graphs batched, virtual id = g*N + node) --
__device__ __align__(16) float g_h[(size_t)NG * NMAX * HROW];
__device__ __align__(16) float g_ad[NG * NMAX * PAD];
__device__ __align__(16) float g_concat[NMAX * NG * HCc];   // [N,216]
__device__ int g_src[NG * EMAX];
__device__ int g_dst[NG * EMAX];
__device__ int g_deg[NG * NMAX];
__device__ int g_off[NG * NMAX + 1];
__device__ int g_cursor[NG * NMAX];
__device__ int g_csr[NG * EMAX];
__device__ int g_bsum[256];
__device__ int g_bofs[256];
__device__ int g_is64;

__device__ __forceinline__ float lrelu(float x) {
    return x > 0.f ? x : NEG_SLOPE * x;
}

// ---------------- K0a: detect edge_index dtype (once; all graphs same) -------
__global__ void k_detect(const int* __restrict__ ei32, int E) {
    __shared__ int ok;
    int t = threadIdx.x;
    if (t == 0) ok = 1;
    __syncthreads();
    int cnt = E < 512 ? E : 512;
    bool z = true;
    for (int i = t; i < cnt; i += blockDim.x)
        if (ei32[2 * i + 1] != 0) z = false;
    if (!z) ok = 0;
    __syncthreads();
    if (t == 0) g_is64 = ok;
}

// ---------------- K0b: zero degree counters (all graphs) ----------------------
__global__ void k_zero(int n3) {
    int i = blockIdx.x * blockDim.x + threadIdx.x;
    if (i < n3) g_deg[i] = 0;
}

// ---------------- K0c: decode + clamp, histogram (blockIdx.y = graph) ---------
__global__ void k_convert_hist(const int* __restrict__ e0,
                               const int* __restrict__ e1,
                               const int* __restrict__ e2, int E, int n) {
    int le = blockIdx.x * blockDim.x + threadIdx.x;
    if (le >= E) return;
    int g = blockIdx.y;
    const int* ei32 = (g == 0) ? e0 : (g == 1) ? e1 : e2;
    long long s, d;
    if (g_is64) {
        const long long* p = (const long long*)ei32;
        s = p[le]; d = p[(size_t)E + le];
    } else {
        s = ei32[le]; d = ei32[(size_t)E + le];
    }
    if (s < 0 || s >= n) s = 0;
    if (d < 0 || d >= n) d = 0;
    int vs = (int)s + g * n, vd = (int)d + g * n;
    size_t ve = (size_t)g * E + le;
    g_src[ve] = vs;
    g_dst[ve] = vd;
    atomicAdd(&g_deg[vd], 1);
}

// ---------------- K0d: 3-phase multi-block exclusive scan ---------------------
__global__ void k_scan_a(int n3) {
    int base = blockIdx.x * SCAN_CHUNK;
    int t = threadIdx.x;
    int s = 0;
    for (int i = t; i < SCAN_CHUNK; i += 256) {
        int idx = base + i;
        if (idx < n3) s += g_deg[idx];
    }
    __shared__ int red[256];
    red[t] = s;
    __syncthreads();
    for (int o = 128; o; o >>= 1) {
        if (t < o) red[t] += red[t + o];
        __syncthreads();
    }
    if (t == 0) g_bsum[blockIdx.x] = red[0];
}
__global__ void k_scan_b(int B) {
    __shared__ int sm[256];
    int t = threadIdx.x;
    sm[t] = (t < B) ? g_bsum[t] : 0;
    __syncthreads();
    for (int o = 1; o < 256; o <<= 1) {
        int v = (t >= o) ? sm[t - o] : 0;
        __syncthreads();
        sm[t] += v;
        __syncthreads();
    }
    if (t < B) g_bofs[t] = (t == 0) ? 0 : sm[t - 1];
}
__global__ void k_scan_c(int n3) {
    int base = blockIdx.x * SCAN_CHUNK;
    int t = threadIdx.x;
    int v[4], s = 0;
    #pragma unroll
    for (int k = 0; k < 4; k++) {
        int idx = base + 4 * t + k;
        v[k] = (idx < n3) ? g_deg[idx] : 0;
        s += v[k];
    }
    __shared__ int sm[256];
    sm[t] = s;
    __syncthreads();
    for (int o = 1; o < 256; o <<= 1) {
        int x = (t >= o) ? sm[t - o] : 0;
        __syncthreads();
        sm[t] += x;
        __syncthreads();
    }
    int run = g_bofs[blockIdx.x] + ((t == 0) ? 0 : sm[t - 1]);
    #pragma unroll
    for (int k = 0; k < 4; k++) {
        int idx = base + 4 * t + k;
        if (idx < n3) {
            g_off[idx] = run;
            g_cursor[idx] = run;
            run += v[k];
            if (idx == n3 - 1) g_off[n3] = run;
        }
    }
}

// ---------------- K0e: scatter src ids into CSR slots -------------------------
__global__ void k_fill(int E3) {
    int e = blockIdx.x * blockDim.x + threadIdx.x;
    if (e >= E3) return;
    int d = g_dst[e];
    int pos = atomicAdd(&g_cursor[d], 1);
    g_csr[pos] = g_src[e];
}

// ---------------- K1: h = x @ W, batched (blockIdx.y = graph) -----------------
__global__ __launch_bounds__(288) void k_linear(
        const float* __restrict__ x0, const float* __restrict__ x1,
        const float* __restrict__ x2,
        const float* __restrict__ W0, const float* __restrict__ W1,
        const float* __restrict__ W2, int n) {
    int g = blockIdx.y;
    const float* x = (g == 0) ? x0 : (g == 1) ? x1 : x2;
    const float* W = (g == 0) ? W0 : (g == 1) ? W1 : W2;
    __shared__ float Ws[128 * HCc];
    __shared__ float xs[16][128];
    int t = threadIdx.x;
    for (int i = t; i < 128 * HCc; i += 288) Ws[i] = W[i];
    int base = blockIdx.x * 16;
    for (int i = t; i < 16 * 128; i += 288) {
        int r = i >> 7, k = i & 127;
        xs[r][k] = (base + r < n) ? x[(size_t)(base + r) * 128 + k] : 0.f;
    }
    __syncthreads();
    int col = t % HCc;
    int r0  = t / HCc;
    #pragma unroll
    for (int rr = 0; rr < 4; rr++) {
        int r = rr * 4 + r0;
        int node = base + r;
        if (node < n) {
            float acc = 0.f;
            #pragma unroll 16
            for (int k = 0; k < 128; k++) acc += xs[r][k] * Ws[k * HCc + col];
            g_h[((size_t)g * n + node) * HROW + col] = acc;
        }
    }
}

// ---------------- K2: attention scalars, batched -------------------------------
__global__ void k_scores(const float* __restrict__ s0, const float* __restrict__ s1,
                         const float* __restrict__ s2,
                         const float* __restrict__ d0, const float* __restrict__ d1,
                         const float* __restrict__ d2, int n) {
    int i = blockIdx.x * blockDim.x + threadIdx.x;
    if (i >= n * NH) return;
    int g = blockIdx.y;
    const float* att_s = (g == 0) ? s0 : (g == 1) ? s1 : s2;
    const float* att_d = (g == 0) ? d0 : (g == 1) ? d1 : d2;
    int node = i / NH, hh = i % NH;
    size_t v = (size_t)g * n + node;
    const float* hp = g_h + v * HROW + hh * 8;
    float as = 0.f, ad = 0.f;
    #pragma unroll
    for (int c = 0; c < 8; c++) {
        float vv = hp[c];
        as += vv * att_s[hh * 8 + c];
        ad += vv * att_d[hh * 8 + c];
    }
    g_h[v * HROW + 72 + hh] = as;
    g_ad[v * PAD + hh] = ad;
}

// ---------------- K3: warp-per-dst GAT softmax-aggregate, batched --------------
__global__ __launch_bounds__(256) void k_gat(
        const float* __restrict__ b0, const float* __restrict__ b1,
        const float* __restrict__ b2, int n) {
    __shared__ float sw[8][32][13];
    int gwarp = (blockIdx.x * 256 + threadIdx.x) >> 5;
    int lane  = threadIdx.x & 31;
    int wib   = threadIdx.x >> 5;
    if (gwarp >= n) return;
    int g = blockIdx.y;
    const float* bias = (g == 0) ? b0 : (g == 1) ? b1 : b2;
    int d = g * n + gwarp;                        // virtual dst id
    int beg = g_off[d], end = g_off[d + 1];

    const float* hd = g_h + (size_t)d * HROW;
    float ad_r[NH], aself_w[NH];
    #pragma unroll
    for (int h = 0; h < NH; h++) {
        ad_r[h]    = g_ad[(size_t)d * PAD + h];
        aself_w[h] = __expf(lrelu(hd[72 + h] + ad_r[h]));
    }
    int h1 = lane >> 3;
    int h2 = (lane + 32) >> 3;

    float dsum[NH];
    #pragma unroll
    for (int h = 0; h < NH; h++) dsum[h] = 0.f;

    float acc1 = aself_w[h1] * hd[lane];
    float acc2 = aself_w[h2] * hd[lane + 32];
    float acc3 = (lane < 8) ? aself_w[8] * hd[lane + 64] : 0.f;

    for (int cbeg = beg; cbeg < end; cbeg += 32) {
        int ecnt = min(32, end - cbeg);
        int s_mine = 0;
        float wv[NH];
        if (lane < ecnt) {
            s_mine = g_csr[cbeg + lane];
            const float* hs = g_h + (size_t)s_mine * HROW;
            float4 p0 = *(const float4*)(hs + 72);
            float4 p1 = *(const float4*)(hs + 76);
            float  a8 = hs[80];
            float asv[NH] = {p0.x, p0.y, p0.z, p0.w, p1.x, p1.y, p1.z, p1.w, a8};
            #pragma unroll
            for (int h = 0; h < NH; h++) {
                wv[h] = __expf(lrelu(asv[h] + ad_r[h]));
                dsum[h] += wv[h];
            }
        } else {
            #pragma unroll
            for (int h = 0; h < NH; h++) wv[h] = 0.f;
        }
        #pragma unroll
        for (int h = 0; h < NH; h++) sw[wib][lane][h] = wv[h];
        __syncwarp();
        for (int j = 0; j < ecnt; j++) {
            int s = __shfl_sync(0xffffffffu, s_mine, j);
            const float* hs = g_h + (size_t)s * HROW;
            acc1 += sw[wib][j][h1] * hs[lane];
            acc2 += sw[wib][j][h2] * hs[lane + 32];
            if (lane < 8) acc3 += sw[wib][j][8] * hs[lane + 64];
        }
        __syncwarp();
    }

    #pragma unroll
    for (int h = 0; h < NH; h++) {
        float v = dsum[h];
        #pragma unroll
        for (int ofs = 16; ofs; ofs >>= 1) v += __shfl_xor_sync(0xffffffffu, v, ofs);
        dsum[h] = v + aself_w[h];
    }

    float* orow = g_concat + (size_t)gwarp * (NG * HCc) + g * HCc;
    orow[lane]      = acc1 / (dsum[h1] + 1e-16f) + bias[lane];
    orow[lane + 32] = acc2 / (dsum[h2] + 1e-16f) + bias[lane + 32];
    if (lane < 8)
        orow[lane + 64] = acc3 / (dsum[8] + 1e-16f) + bias[lane + 64];
}

// ---------------- K4: relu -> [216,2] FNN -> softmax ---------------------------
__global__ void k_fnn(const float* __restrict__ fW, const float* __restrict__ fb,
                      float* __restrict__ out, int n) {
    __shared__ float Wl[NG * HCc * 2];
    int t = threadIdx.x;
    for (int i = t; i < NG * HCc * 2; i += blockDim.x) Wl[i] = fW[i];
    __syncthreads();
    int node = blockIdx.x * blockDim.x + t;
    if (node >= n) return;
    const float* row = g_concat + (size_t)node * (NG * HCc);
    float l0 = fb[0], l1 = fb[1];
    #pragma unroll 8
    for (int i = 0; i < NG * HCc; i++) {
        float v = row[i];
        v = v > 0.f ? v : 0.f;
        l0 += v * Wl[2 * i];
        l1 += v * Wl[2 * i + 1];
    }
    float mm = fmaxf(l0, l1);
    float e0 = __expf(l0 - mm), e1 = __expf(l1 - mm);
    float inv = 1.f / (e0 + e1);
    out[2 * node]     = e0 * inv;
    out[2 * node + 1] = e1 * inv;
}

// ---------------- host ---------------------------------------------------------
extern "C" void kernel_launch(void* const* d_in, const int* in_sizes, int n_in,
                              void* d_out, int out_size) {
    const float* x[3]   = {0, 0, 0};
    const int*   ei[3]  = {0, 0, 0};
    const float* W[3]   = {0, 0, 0};
    const float* asr[3] = {0, 0, 0};
    const float* adr[3] = {0, 0, 0};
    const float* b[3]   = {0, 0, 0};
    const float* fW = 0; const float* fb = 0;
    int ix = 0, ie = 0, iw = 0, cur = 0, c72 = 0;
    long long xsz = 0, esz = 0;

    for (int i = 0; i < n_in; i++) {
        long long sz = in_sizes[i];
        if (sz >= 1000000) {
            if (sz > 4000000) {
                if (ix < 3) { x[ix++] = (const float*)d_in[i]; xsz = sz; }
            } else {
                if (ie < 3) { ei[ie++] = (const int*)d_in[i]; esz = sz; }
            }
        } else if (sz == 128 * HCc) {
            if (iw < 3) { W[iw] = (const float*)d_in[i]; cur = iw; iw++; c72 = 0; }
        } else if (sz == HCc) {
            if (c72 == 0)      asr[cur] = (const float*)d_in[i];
            else if (c72 == 1) adr[cur] = (const float*)d_in[i];
            else               b[cur]   = (const float*)d_in[i];
            c72++;
        } else if (sz == NG * HCc * 2) {
            fW = (const float*)d_in[i];
        } else if (sz == 2) {
            fb = (const float*)d_in[i];
        }
    }

    int N = (int)(xsz / 128);
    int E = (int)(esz / 2);
    int n3 = NG * N, E3 = NG * E;
    float* out = (float*)d_out;

    dim3 gE((E + 255) / 256, NG);
    dim3 gLin((N + 15) / 16, NG);
    dim3 gSc((N * NH + 255) / 256, NG);
    dim3 gGat((N + 7) / 8, NG);
    int bN3 = (n3 + 255) / 256;
    int bE3 = (E3 + 255) / 256;
    int B = (n3 + SCAN_CHUNK - 1) / SCAN_CHUNK;

    k_detect      <<<1, 256>>>(ei[0], E);
    k_zero        <<<bN3, 256>>>(n3);
    k_convert_hist<<<gE, 256>>>(ei[0], ei[1], ei[2], E, N);
    k_scan_a      <<<B, 256>>>(n3);
    k_scan_b      <<<1, 256>>>(B);
    k_scan_c      <<<B, 256>>>(n3);
    k_fill        <<<bE3, 256>>>(E3);
    k_linear      <<<gLin, 288>>>(x[0], x[1], x[2], W[0], W[1], W[2], N);
    k_scores      <<<gSc, 256>>>(asr[0], asr[1], asr[2], adr[0], adr[1], adr[2], N);
    k_gat         <<<gGat, 256>>>(b[0], b[1], b[2], N);
    k_fnn         <<<(N + 255) / 256, 256>>>(fW, fb, out, N);
    (void)out_size;
}